// round 7
// baseline (speedup 1.0000x reference)
#include <cuda_runtime.h>
#include <stdint.h>

#define BB 4
#define QQ 256
#define MMM 256
#define HH 512
#define DQS 512
#define DKS 512
#define DC (DQS + DKS)

// Scratch device globals
__device__ float g_qproj[BB * QQ * HH];    // 2 MB
__device__ float g_kproj[BB * MMM * HH];   // 2 MB
__device__ float g_logits[BB * QQ * MMM];  // 1 MB
__device__ float g_partial[BB * QQ * DQS]; // 2 MB  query @ Wo1^T + bo
__device__ float g_P2[BB * MMM * DQS];     // 2 MB  memory @ Wo2^T

// ---------------------------------------------------------------------------
// tf32 / f16x2 helpers
// ---------------------------------------------------------------------------
__device__ __forceinline__ float f2tf32(float x) {
    uint32_t r;
    asm("cvt.rna.tf32.f32 %0, %1;" : "=r"(r) : "f"(x));
    return __uint_as_float(r);
}
__device__ __forceinline__ uint32_t fu(float x) { return __float_as_uint(x); }

__device__ __forceinline__ uint32_t pack_f16x2(float hi, float lo) {
    uint32_t r;
    asm("cvt.rn.f16x2.f32 %0, %1, %2;" : "=r"(r) : "f"(hi), "f"(lo));
    return r;
}

__device__ __forceinline__ void mma_tf32(float c[4], const uint32_t a[4],
                                         const uint32_t b[2]) {
    asm volatile(
        "mma.sync.aligned.m16n8k8.row.col.f32.tf32.tf32.f32 "
        "{%0,%1,%2,%3}, {%4,%5,%6,%7}, {%8,%9}, {%0,%1,%2,%3};"
        : "+f"(c[0]), "+f"(c[1]), "+f"(c[2]), "+f"(c[3])
        : "r"(a[0]), "r"(a[1]), "r"(a[2]), "r"(a[3]), "r"(b[0]), "r"(b[1]));
}

// ---------------------------------------------------------------------------
// NT tf32 GEMM body, 256 threads, 64x64 tile, BK=32, DOUBLE-BUFFERED smem.
// 8 warps (2x4), warp tile 32x16. Stride 36 -> conflict-free fragment LDS.
// ---------------------------------------------------------------------------
template<bool BIAS>
__device__ __forceinline__ void gemm_nt_256(
    float (*Asb)[64][36], float (*Wsb)[64][36],
    int row0, int col0,
    const float* __restrict__ A, int lda,
    const float* __restrict__ W, int ldw,
    const float* __restrict__ bias,
    float* __restrict__ C, int ldc, int K)
{
    const int tid  = threadIdx.x;
    const int lane = tid & 31;
    const int g    = lane >> 2;
    const int tg   = lane & 3;
    const int w    = tid >> 5;
    const int wm   = (w >> 2) << 5;
    const int wn   = (w & 3) << 4;

    int lr[2], lc[2];
#pragma unroll
    for (int c = 0; c < 2; c++) {
        int idx = tid + (c << 8);
        lr[c] = idx >> 3;
        lc[c] = (idx & 7) << 2;
    }

    float acc[2][2][4];
#pragma unroll
    for (int mi = 0; mi < 2; mi++)
#pragma unroll
        for (int ni = 0; ni < 2; ni++)
#pragma unroll
            for (int j = 0; j < 4; j++) acc[mi][ni][j] = 0.f;

    float4 pa[2], pw[2];
#pragma unroll
    for (int c = 0; c < 2; c++) {
        pa[c] = *reinterpret_cast<const float4*>(A + (size_t)(row0 + lr[c]) * lda + lc[c]);
        pw[c] = *reinterpret_cast<const float4*>(W + (size_t)(col0 + lr[c]) * ldw + lc[c]);
    }

    int buf = 0;
    for (int k0 = 0; k0 < K; k0 += 32) {
#pragma unroll
        for (int c = 0; c < 2; c++) {
            float4 va = pa[c], vw = pw[c];
            *reinterpret_cast<float4*>(&Asb[buf][lr[c]][lc[c]]) =
                make_float4(f2tf32(va.x), f2tf32(va.y), f2tf32(va.z), f2tf32(va.w));
            *reinterpret_cast<float4*>(&Wsb[buf][lr[c]][lc[c]]) =
                make_float4(f2tf32(vw.x), f2tf32(vw.y), f2tf32(vw.z), f2tf32(vw.w));
        }
        __syncthreads();

        int kn = k0 + 32;
        if (kn < K) {
#pragma unroll
            for (int c = 0; c < 2; c++) {
                pa[c] = *reinterpret_cast<const float4*>(
                    A + (size_t)(row0 + lr[c]) * lda + kn + lc[c]);
                pw[c] = *reinterpret_cast<const float4*>(
                    W + (size_t)(col0 + lr[c]) * ldw + kn + lc[c]);
            }
        }

#pragma unroll
        for (int ks = 0; ks < 4; ks++) {
            const int kk = ks << 3;
            uint32_t af[2][4], bf[2][2];
#pragma unroll
            for (int mi = 0; mi < 2; mi++) {
                int r = wm + (mi << 4) + g;
                af[mi][0] = fu(Asb[buf][r][kk + tg]);
                af[mi][1] = fu(Asb[buf][r + 8][kk + tg]);
                af[mi][2] = fu(Asb[buf][r][kk + tg + 4]);
                af[mi][3] = fu(Asb[buf][r + 8][kk + tg + 4]);
            }
#pragma unroll
            for (int ni = 0; ni < 2; ni++) {
                int cn = wn + (ni << 3) + g;
                bf[ni][0] = fu(Wsb[buf][cn][kk + tg]);
                bf[ni][1] = fu(Wsb[buf][cn][kk + tg + 4]);
            }
#pragma unroll
            for (int mi = 0; mi < 2; mi++)
#pragma unroll
                for (int ni = 0; ni < 2; ni++)
                    mma_tf32(acc[mi][ni], af[mi], bf[ni]);
        }
        buf ^= 1;
    }

#pragma unroll
    for (int mi = 0; mi < 2; mi++) {
#pragma unroll
        for (int ni = 0; ni < 2; ni++) {
            int col = col0 + wn + (ni << 3) + (tg << 1);
            float b0 = 0.f, b1 = 0.f;
            if (BIAS) { b0 = bias[col]; b1 = bias[col + 1]; }
            int r0 = row0 + wm + (mi << 4) + g;
            int r1 = r0 + 8;
            *reinterpret_cast<float2*>(C + (size_t)r0 * ldc + col) =
                make_float2(acc[mi][ni][0] + b0, acc[mi][ni][1] + b1);
            *reinterpret_cast<float2*>(C + (size_t)r1 * ldc + col) =
                make_float2(acc[mi][ni][2] + b0, acc[mi][ni][3] + b1);
        }
    }
}

// ---------------------------------------------------------------------------
// K1: qproj + kproj. 256 blocks x 256 thr.
// ---------------------------------------------------------------------------
__global__ void __launch_bounds__(256) k1_proj(
    const float* __restrict__ query, const float* __restrict__ memory,
    const float* __restrict__ Wq, const float* __restrict__ bq,
    const float* __restrict__ Wk, const float* __restrict__ bk)
{
    __shared__ float As[2][64][36];
    __shared__ float Ws[2][64][36];
    const int t = blockIdx.x & 127;
    const int row0 = (t >> 3) << 6;
    const int col0 = (t & 7) << 6;
    if (blockIdx.x < 128)
        gemm_nt_256<true>(As, Ws, row0, col0, query, DQS, Wq, DQS, bq,
                          g_qproj, HH, DQS);
    else
        gemm_nt_256<true>(As, Ws, row0, col0, memory, DKS, Wk, DKS, bk,
                          g_kproj, HH, DKS);
}

// ---------------------------------------------------------------------------
// Scores body: f16x2 tanh (2 tanhs / MUFU op). 256 thr = 8 warps;
// warp owns one q-row, block covers 8 q-rows x 64 m.
// Products accumulated via fma.rn.f16x2; both halves summed at the end
// (order-independent pairing with identically-packed Wl).
// ---------------------------------------------------------------------------
__device__ __forceinline__ void scores_body(int bid, float (*ks)[512],
                                            const float* __restrict__ Wl)
{
    const int b  = bid >> 7;
    const int qg = (bid >> 2) & 31;
    const int mg = bid & 3;
    const int q0 = qg << 3;
    const int m0base = mg << 6;

    const int tid = threadIdx.x;
    const int lane = tid & 31;
    const int w = tid >> 5;
    const int q = q0 + w;

    float qr[16];
    uint32_t wlp[8];
    const float* qp = g_qproj + ((size_t)(b * QQ + q)) * HH;
#pragma unroll
    for (int j = 0; j < 16; j++) qr[j] = qp[lane + 32 * j];
#pragma unroll
    for (int jp = 0; jp < 8; jp++)
        wlp[jp] = pack_f16x2(Wl[lane + 64 * jp + 32], Wl[lane + 64 * jp]);

    float* lout = g_logits + ((size_t)(b * QQ + q)) * MMM;

    for (int t = 0; t < 4; t++) {
        const int m0 = m0base + (t << 4);
        __syncthreads();
        const float* kp = g_kproj + ((size_t)(b * MMM + m0)) * HH;
#pragma unroll
        for (int i = 0; i < 8; i++) {
            int idx = tid + (i << 8);
            int mm = idx >> 7;
            int c4 = (idx & 127) << 2;
            *reinterpret_cast<float4*>(&ks[mm][c4]) =
                *reinterpret_cast<const float4*>(kp + mm * HH + c4);
        }
        __syncthreads();

#pragma unroll 4
        for (int mm = 0; mm < 16; mm++) {
            uint32_t acch = 0;   // f16x2 {+0, +0}
#pragma unroll
            for (int jp = 0; jp < 8; jp++) {
                float s0 = qr[2 * jp]     + ks[mm][lane + 64 * jp];
                float s1 = qr[2 * jp + 1] + ks[mm][lane + 64 * jp + 32];
                uint32_t sp = pack_f16x2(s1, s0);
                uint32_t tp;
                asm("tanh.approx.f16x2 %0, %1;" : "=r"(tp) : "r"(sp));
                asm("fma.rn.f16x2 %0, %1, %2, %0;" : "+r"(acch)
                    : "r"(tp), "r"(wlp[jp]));
            }
            float flo, fhi;
            asm("{ .reg .b16 l, h;\n"
                "  mov.b32 {l, h}, %2;\n"
                "  cvt.f32.f16 %0, l;\n"
                "  cvt.f32.f16 %1, h; }"
                : "=f"(flo), "=f"(fhi) : "r"(acch));
            float acc = flo + fhi;
#pragma unroll
            for (int o = 16; o > 0; o >>= 1)
                acc += __shfl_xor_sync(0xFFFFFFFFu, acc, o);
            if (lane == 0) lout[m0 + mm] = acc;
        }
    }
}

// ---------------------------------------------------------------------------
// K2: scores (512 blocks) + partial = query@Wo1^T + bo (128) +
//     P2 = memory@Wo2^T (128). GEMMs ride tensor pipe under MUFU scores.
// ---------------------------------------------------------------------------
__global__ void __launch_bounds__(256) k2_scores_fused(
    const float* __restrict__ query, const float* __restrict__ memory,
    const float* __restrict__ Wo, const float* __restrict__ bo,
    const float* __restrict__ Wl)
{
    __shared__ __align__(16) union {
        float ks[16][512];                                   // 32 KB
        struct { float As[2][64][36]; float Ws[2][64][36]; } g;  // 36.9 KB
    } sm;

    const int bid = blockIdx.x;
    if (bid < 512) {
        scores_body(bid, sm.ks, Wl);
    } else if (bid < 640) {
        const int t = bid - 512;
        const int row0 = (t >> 3) << 6;
        const int col0 = (t & 7) << 6;
        gemm_nt_256<true>(sm.g.As, sm.g.Ws, row0, col0,
                          query, DQS, Wo, DC, bo, g_partial, DQS, DQS);
    } else {
        const int t = bid - 640;
        const int row0 = (t >> 3) << 6;
        const int col0 = (t & 7) << 6;
        gemm_nt_256<false>(sm.g.As, sm.g.Ws, row0, col0,
                           memory, DKS, Wo + DQS, DC, nullptr, g_P2, DQS, DKS);
    }
}

// ---------------------------------------------------------------------------
// K3: softmax. 256 blocks x 128 threads, warp per q-row.
// ---------------------------------------------------------------------------
__global__ void __launch_bounds__(128) k3_softmax(
    const unsigned int* __restrict__ mask,
    float* __restrict__ weights)
{
    const int bid = blockIdx.x;
    const int b = bid >> 6;
    const int lane = threadIdx.x & 31;
    const int w = threadIdx.x >> 5;
    const int q = ((bid & 63) << 2) + w;

    const float* lin = g_logits + ((size_t)(b * QQ + q)) * MMM;
    const unsigned int* mrow = mask + b * MMM;

    float v[8];
    float mx = -3.4e38f;
#pragma unroll
    for (int j = 0; j < 8; j++) {
        int m = lane + 32 * j;
        float s = lin[m];
        if (mrow[m] != 0u) s = -1e18f;
        v[j] = s;
        mx = fmaxf(mx, s);
    }
#pragma unroll
    for (int o = 16; o > 0; o >>= 1)
        mx = fmaxf(mx, __shfl_xor_sync(0xFFFFFFFFu, mx, o));
    float sum = 0.f;
#pragma unroll
    for (int j = 0; j < 8; j++) {
        v[j] = __expf(v[j] - mx);
        sum += v[j];
    }
#pragma unroll
    for (int o = 16; o > 0; o >>= 1)
        sum += __shfl_xor_sync(0xFFFFFFFFu, sum, o);
    float inv = 1.f / sum;

    float* wout = weights + ((size_t)(b * QQ + q)) * MMM;
#pragma unroll
    for (int j = 0; j < 8; j++)
        wout[lane + 32 * j] = v[j] * inv;
}

// ---------------------------------------------------------------------------
// K4f: out = tanh(partial + weights @ P2)  (batched NN, K = 256).
// 256 thr, 64x64 tile, double-buffered. grid = 128 blocks.
// ---------------------------------------------------------------------------
__global__ void __launch_bounds__(256) k4_final(
    const float* __restrict__ Wt, float* __restrict__ out)
{
    const int bid = blockIdx.x;
    const int b = bid >> 5;
    const int tile = bid & 31;
    const int row0 = (tile >> 3) << 6;
    const int col0 = (tile & 7) << 6;

    const float* A  = Wt   + (size_t)b * QQ * MMM;
    const float* Bm = g_P2 + (size_t)b * MMM * DQS;

    __shared__ float As[2][64][36];
    __shared__ float Bs[2][32][72];

    const int tid  = threadIdx.x;
    const int lane = tid & 31;
    const int g    = lane >> 2;
    const int tg   = lane & 3;
    const int w    = tid >> 5;
    const int wm   = (w >> 2) << 5;
    const int wn   = (w & 3) << 4;

    int ar[2], ac[2], br[2], bc[2];
#pragma unroll
    for (int c = 0; c < 2; c++) {
        int idx = tid + (c << 8);
        ar[c] = idx >> 3;  ac[c] = (idx & 7) << 2;
        br[c] = idx >> 4;  bc[c] = (idx & 15) << 2;
    }

    float acc[2][2][4];
#pragma unroll
    for (int mi = 0; mi < 2; mi++)
#pragma unroll
        for (int ni = 0; ni < 2; ni++)
#pragma unroll
            for (int j = 0; j < 4; j++) acc[mi][ni][j] = 0.f;

    float4 pa[2], pb[2];
#pragma unroll
    for (int c = 0; c < 2; c++) {
        pa[c] = *reinterpret_cast<const float4*>(A + (size_t)(row0 + ar[c]) * MMM + ac[c]);
        pb[c] = *reinterpret_cast<const float4*>(Bm + (size_t)br[c] * DQS + col0 + bc[c]);
    }

    int buf = 0;
    for (int k0 = 0; k0 < MMM; k0 += 32) {
#pragma unroll
        for (int c = 0; c < 2; c++) {
            float4 va = pa[c], vb = pb[c];
            *reinterpret_cast<float4*>(&As[buf][ar[c]][ac[c]]) =
                make_float4(f2tf32(va.x), f2tf32(va.y), f2tf32(va.z), f2tf32(va.w));
            *reinterpret_cast<float4*>(&Bs[buf][br[c]][bc[c]]) =
                make_float4(f2tf32(vb.x), f2tf32(vb.y), f2tf32(vb.z), f2tf32(vb.w));
        }
        __syncthreads();

        int kn = k0 + 32;
        if (kn < MMM) {
#pragma unroll
            for (int c = 0; c < 2; c++) {
                pa[c] = *reinterpret_cast<const float4*>(
                    A + (size_t)(row0 + ar[c]) * MMM + kn + ac[c]);
                pb[c] = *reinterpret_cast<const float4*>(
                    Bm + (size_t)(kn + br[c]) * DQS + col0 + bc[c]);
            }
        }

#pragma unroll
        for (int ks = 0; ks < 4; ks++) {
            const int kk = ks << 3;
            uint32_t af[2][4], bf[2][2];
#pragma unroll
            for (int mi = 0; mi < 2; mi++) {
                int r = wm + (mi << 4) + g;
                af[mi][0] = fu(As[buf][r][kk + tg]);
                af[mi][1] = fu(As[buf][r + 8][kk + tg]);
                af[mi][2] = fu(As[buf][r][kk + tg + 4]);
                af[mi][3] = fu(As[buf][r + 8][kk + tg + 4]);
            }
#pragma unroll
            for (int ni = 0; ni < 2; ni++) {
                int cn = wn + (ni << 3) + g;
                bf[ni][0] = fu(Bs[buf][kk + tg][cn]);
                bf[ni][1] = fu(Bs[buf][kk + tg + 4][cn]);
            }
#pragma unroll
            for (int mi = 0; mi < 2; mi++)
#pragma unroll
                for (int ni = 0; ni < 2; ni++)
                    mma_tf32(acc[mi][ni], af[mi], bf[ni]);
        }
        buf ^= 1;
    }

#pragma unroll
    for (int mi = 0; mi < 2; mi++) {
#pragma unroll
        for (int ni = 0; ni < 2; ni++) {
            int col = col0 + wn + (ni << 3) + (tg << 1);
            size_t r0 = (size_t)b * QQ + row0 + wm + (mi << 4) + g;
            size_t r1 = r0 + 8;
            float2 p0 = *reinterpret_cast<const float2*>(&g_partial[r0 * DQS + col]);
            float2 p1 = *reinterpret_cast<const float2*>(&g_partial[r1 * DQS + col]);
            *reinterpret_cast<float2*>(out + r0 * DQS + col) =
                make_float2(tanhf(acc[mi][ni][0] + p0.x), tanhf(acc[mi][ni][1] + p0.y));
            *reinterpret_cast<float2*>(out + r1 * DQS + col) =
                make_float2(tanhf(acc[mi][ni][2] + p1.x), tanhf(acc[mi][ni][3] + p1.y));
        }
    }
}

// ---------------------------------------------------------------------------
// Launch
// ---------------------------------------------------------------------------
extern "C" void kernel_launch(void* const* d_in, const int* in_sizes, int n_in,
                              void* d_out, int out_size)
{
    const float* query  = (const float*)d_in[0];
    const float* memory = (const float*)d_in[1];
    const unsigned int* mask = (const unsigned int*)d_in[2];
    const float* Wk = (const float*)d_in[3];
    const float* bk = (const float*)d_in[4];
    const float* Wq = (const float*)d_in[5];
    const float* bq = (const float*)d_in[6];
    const float* Wl = (const float*)d_in[7];
    // d_in[8] = bl (uniform shift — cancels in softmax)
    const float* Wo = (const float*)d_in[9];
    const float* bo = (const float*)d_in[10];

    float* out     = (float*)d_out;
    float* weights = out + BB * QQ * DQS;

    k1_proj<<<256, 256>>>(query, memory, Wq, bq, Wk, bk);
    k2_scores_fused<<<768, 256>>>(query, memory, Wo, bo, Wl);
    k3_softmax<<<256, 128>>>(mask, weights);
    k4_final<<<128, 256>>>(weights, out);
}